// round 9
// baseline (speedup 1.0000x reference)
#include <cuda_runtime.h>
#include <math.h>

#define T 32
#define N 512
#define E 64
#define F 64
#define HD 64
#define SLOPE 0.2f

// ---------------- device scratch ----------------
__device__ float g_h[T * N * HD];       // 4 MB
__device__ float g_shyp[T * N];
__device__ float g_sind[T * N];
__device__ float g_emax[T * E];
__device__ float g_einv[T * E];
__device__ float g_ind[T * N * HD];     // 4 MB
__device__ int   g_adj_cnt[N];
__device__ int   g_adj_nbr[N * N];
__device__ int   g_ne_cnt[N];
__device__ int   g_ne_off[N];
__device__ int   g_ne_lst[N * E];
__device__ int   g_en_cnt[E];
__device__ int   g_en_lst[E * N];
__device__ int   g_wl_n[N * E];
__device__ int   g_wl_e[N * E];
__device__ int   g_nnz;
__device__ int   g_Mhyp;
__device__ int   g_Mtot;
__device__ float g_zall[T * N * E + T * N];
__device__ float g_feats[T * N * E * HD];   // worst-case sized; ~12 MB live (L2-resident)

// fast math: tolerance is 1e-3, __expf rel err ~1e-6
__device__ __forceinline__ float fexp(float v) { return __expf(v); }
__device__ __forceinline__ float elu1(float v) { return v > 0.f ? v : __expf(v) - 1.0f; }

// ---------------- fused front: h-GEMM + all CSR builds + scan (block-specialized) ----------------
__global__ void __launch_bounds__(256) k_front(const float* __restrict__ x,
                                               const float* __restrict__ W,
                                               const float* __restrict__ ah,
                                               const float* __restrict__ ai,
                                               const int* __restrict__ adj,
                                               const int* __restrict__ Hm) {
    int b = blockIdx.x;
    int tid = threadIdx.x;
    int lane = tid & 31;
    int wrp = tid >> 5;

    if (b < 512) {
        __shared__ float xs[32][65];
        __shared__ float ws[64][65];
        int r0 = b * 32;

        for (int i = tid; i < 32 * 64; i += 256) {
            int r = i >> 6, c = i & 63;
            xs[r][c] = x[(r0 + r) * F + c];
        }
        for (int i = tid; i < 64 * 64; i += 256) {
            int r = i >> 6, c = i & 63;
            ws[r][c] = W[i];
        }
        __syncthreads();

        int ty = tid >> 4, tx = tid & 15;
        float acc[2][4] = {{0.f,0.f,0.f,0.f},{0.f,0.f,0.f,0.f}};
        #pragma unroll 8
        for (int k = 0; k < 64; k++) {
            float xr0 = xs[ty * 2 + 0][k];
            float xr1 = xs[ty * 2 + 1][k];
            float wv[4];
            #pragma unroll
            for (int j = 0; j < 4; j++) wv[j] = ws[k][tx * 4 + j];
            #pragma unroll
            for (int j = 0; j < 4; j++) {
                acc[0][j] = fmaf(xr0, wv[j], acc[0][j]);
                acc[1][j] = fmaf(xr1, wv[j], acc[1][j]);
            }
        }
        __syncthreads();
        #pragma unroll
        for (int i = 0; i < 2; i++) {
            int r = ty * 2 + i;
            #pragma unroll
            for (int j = 0; j < 4; j++) xs[r][tx * 4 + j] = acc[i][j];
            float4 v = make_float4(acc[i][0], acc[i][1], acc[i][2], acc[i][3]);
            *(float4*)&g_h[(r0 + r) * HD + tx * 4] = v;
        }
        __syncthreads();

        int row = tid >> 3, oct = tid & 7;
        float sh = 0.f, si = 0.f;
        #pragma unroll
        for (int k = 0; k < 8; k++) {
            float v = xs[row][oct * 8 + k];
            sh = fmaf(v, __ldg(&ah[oct * 8 + k]), sh);
            si = fmaf(v, __ldg(&ai[oct * 8 + k]), si);
        }
        #pragma unroll
        for (int o = 4; o > 0; o >>= 1) {
            sh += __shfl_xor_sync(0xffffffffu, sh, o);
            si += __shfl_xor_sync(0xffffffffu, si, o);
        }
        if (oct == 0) {
            g_shyp[r0 + row] = sh >= 0.f ? sh : SLOPE * sh;
            g_sind[r0 + row] = si >= 0.f ? si : SLOPE * si;
        }
    } else if (b < 576) {                      // adjacency CSR
        int i = (b - 512) * 8 + wrp;
        int cnt = 0;
        #pragma unroll
        for (int c = 0; c < N / 32; c++) {
            int j = c * 32 + lane;
            bool m = adj[i * N + j] != 0;
            unsigned bl = __ballot_sync(0xffffffffu, m);
            if (m) g_adj_nbr[i * N + cnt + __popc(bl & ((1u << lane) - 1u))] = j;
            cnt += __popc(bl);
        }
        if (lane == 0) g_adj_cnt[i] = cnt;
    } else if (b < 584) {                      // edge -> member nodes
        int e = (b - 576) * 8 + wrp;
        int cnt = 0;
        #pragma unroll
        for (int c = 0; c < N / 32; c++) {
            int n = c * 32 + lane;
            bool m = Hm[n * E + e] != 0;
            unsigned bl = __ballot_sync(0xffffffffu, m);
            if (m) g_en_lst[e * N + cnt + __popc(bl & ((1u << lane) - 1u))] = n;
            cnt += __popc(bl);
        }
        if (lane == 0) g_en_cnt[e] = cnt;
    } else {                                   // node->edge CSR + scan + worklist
        __shared__ int buf[256];
        int n0 = tid * 2, n1 = tid * 2 + 1;
        int c0 = 0, c1 = 0;
        #pragma unroll
        for (int e = 0; e < E; e++) {
            if (Hm[n0 * E + e] != 0) g_ne_lst[n0 * E + (c0++)] = e;
            if (Hm[n1 * E + e] != 0) g_ne_lst[n1 * E + (c1++)] = e;
        }
        g_ne_cnt[n0] = c0;
        g_ne_cnt[n1] = c1;
        buf[tid] = c0 + c1;
        __syncthreads();
        #pragma unroll
        for (int o = 1; o < 256; o <<= 1) {
            int add = (tid >= o) ? buf[tid - o] : 0;
            __syncthreads();
            buf[tid] += add;
            __syncthreads();
        }
        int S = buf[tid];
        int off0 = S - c0 - c1;
        int off1 = off0 + c0;
        g_ne_off[n0] = off0;
        g_ne_off[n1] = off1;
        if (tid == 255) {
            int nnz = S;
            g_nnz = nnz;
            g_Mhyp = T * nnz;
            g_Mtot = T * nnz + T * N;
        }
        for (int j = 0; j < c0; j++) {
            g_wl_n[off0 + j] = n0;
            g_wl_e[off0 + j] = g_ne_lst[n0 * E + j];
        }
        for (int j = 0; j < c1; j++) {
            g_wl_n[off1 + j] = n1;
            g_wl_e[off1 + j] = g_ne_lst[n1 * E + j];
        }
    }
}

// ---------------- fused: industry (warp-per-row, 8-wide MLP) + hyperedge stats ----------------
__global__ void __launch_bounds__(256) k_mid() {
    int b = blockIdx.x;
    int tid = threadIdx.x;
    int lane = tid & 31;
    int wrp = tid >> 5;
    if (b < 2048) {
        __shared__ float smw[8][512];
        int row = b * 8 + wrp;
        int t = row >> 9;
        int i = row & (N - 1);
        int deg = g_adj_cnt[i];
        const int* nbr = g_adj_nbr + i * N;
        const float* si = g_sind + t * N;

        float m = -3.0e38f;
        for (int k = lane; k < deg; k += 32) m = fmaxf(m, si[nbr[k]]);
        #pragma unroll
        for (int o = 16; o > 0; o >>= 1) m = fmaxf(m, __shfl_xor_sync(0xffffffffu, m, o));
        float s = 0.f;
        for (int k = lane; k < deg; k += 32) {
            float w = fexp(si[nbr[k]] - m);
            smw[wrp][k] = w;
            s += w;
        }
        #pragma unroll
        for (int o = 16; o > 0; o >>= 1) s += __shfl_xor_sync(0xffffffffu, s, o);
        float inv = 1.f / s;
        __syncwarp();

        const float* hb = g_h + t * N * HD;
        float2 ac[8];
        #pragma unroll
        for (int u = 0; u < 8; u++) ac[u] = make_float2(0.f, 0.f);
        int k = 0;
        for (; k + 8 <= deg; k += 8) {
            #pragma unroll
            for (int u = 0; u < 8; u++) {
                float w = smw[wrp][k + u];
                float2 hv = *(const float2*)&hb[nbr[k + u] * HD + lane * 2];
                ac[u].x = fmaf(w, hv.x, ac[u].x);
                ac[u].y = fmaf(w, hv.y, ac[u].y);
            }
        }
        for (; k < deg; k++) {
            float w = smw[wrp][k];
            float2 hv = *(const float2*)&hb[nbr[k] * HD + lane * 2];
            ac[0].x = fmaf(w, hv.x, ac[0].x);
            ac[0].y = fmaf(w, hv.y, ac[0].y);
        }
        float2 r;
        r.x = (((ac[0].x + ac[1].x) + (ac[2].x + ac[3].x)) +
               ((ac[4].x + ac[5].x) + (ac[6].x + ac[7].x))) * inv;
        r.y = (((ac[0].y + ac[1].y) + (ac[2].y + ac[3].y)) +
               ((ac[4].y + ac[5].y) + (ac[6].y + ac[7].y))) * inv;
        *(float2*)&g_ind[row * HD + lane * 2] = r;
    } else {
        int w = (b - 2048) * 8 + wrp;
        int t = w / E, e = w % E;
        int cnt = g_en_cnt[e];
        const int* lst = g_en_lst + e * N;
        const float* sh = g_shyp + t * N;
        float m = -3.0e38f;
        for (int i = lane; i < cnt; i += 32) m = fmaxf(m, sh[lst[i]]);
        #pragma unroll
        for (int o = 16; o > 0; o >>= 1) m = fmaxf(m, __shfl_xor_sync(0xffffffffu, m, o));
        float s = 0.f;
        for (int i = lane; i < cnt; i += 32) s += fexp(sh[lst[i]] - m);
        #pragma unroll
        for (int o = 16; o > 0; o >>= 1) s += __shfl_xor_sync(0xffffffffu, s, o);
        if (lane == 0) { g_emax[w] = m; g_einv[w] = 1.f / s; }
    }
}

// ---------------- phase A: 128-row tiles; stores hyper feats rows to g_feats ----------------
__global__ void __launch_bounds__(256) k_scoreA(const float* __restrict__ Wc1g,
                                                const float* __restrict__ bc1g,
                                                const float* __restrict__ wc2g,
                                                const float* __restrict__ bc2g) {
    __shared__ float Ws[HD * HD];              // 16 KB
    __shared__ float fsT[HD * 128];            // 32 KB, [k][row]
    int tid = threadIdx.x;
    int tx = tid & 15, ty = tid >> 4;
    int r = tid & 127, half = tid >> 7;

    for (int i = tid; i < HD * HD; i += 256) Ws[i] = Wc1g[i];
    float bc1r[4], wc2r[4];
    #pragma unroll
    for (int j = 0; j < 4; j++) {
        bc1r[j] = __ldg(&bc1g[tx * 4 + j]);
        wc2r[j] = __ldg(&wc2g[tx * 4 + j]);
    }
    float bc2 = __ldg(&bc2g[0]);
    int Mtot = g_Mtot, Mhyp = g_Mhyp, nnz = g_nnz;
    int ntiles = (Mtot + 127) >> 7;

    for (int tile = blockIdx.x; tile < ntiles; tile += gridDim.x) {
        __syncthreads();
        int row = tile * 128 + r;
        int kb = half * 32;
        if (row < Mhyp) {
            int t = row / nnz;
            int idx = row - t * nnz;
            int n = g_wl_n[idx], e = g_wl_e[idx];
            float a = fexp(g_shyp[t * N + n] - g_emax[t * E + e]) * g_einv[t * E + e];
            const float4* hp = (const float4*)&g_h[(t * N + n) * HD + kb];
            float4* fo = (float4*)&g_feats[row * HD + kb];
            #pragma unroll
            for (int q = 0; q < 8; q++) {
                float4 v = hp[q];
                float4 f;
                f.x = elu1(a * v.x);
                f.y = elu1(a * v.y);
                f.z = elu1(a * v.z);
                f.w = elu1(a * v.w);
                fsT[(kb + q * 4 + 0) * 128 + r] = f.x;
                fsT[(kb + q * 4 + 1) * 128 + r] = f.y;
                fsT[(kb + q * 4 + 2) * 128 + r] = f.z;
                fsT[(kb + q * 4 + 3) * 128 + r] = f.w;
                fo[q] = f;
            }
        } else if (row < Mtot) {
            const float4* ip = (const float4*)&g_ind[(row - Mhyp) * HD + kb];
            #pragma unroll
            for (int q = 0; q < 8; q++) {
                float4 v = ip[q];
                fsT[(kb + q * 4 + 0) * 128 + r] = v.x;
                fsT[(kb + q * 4 + 1) * 128 + r] = v.y;
                fsT[(kb + q * 4 + 2) * 128 + r] = v.z;
                fsT[(kb + q * 4 + 3) * 128 + r] = v.w;
            }
        } else {
            #pragma unroll
            for (int q = 0; q < 32; q++) fsT[(kb + q) * 128 + r] = 0.f;
        }
        __syncthreads();

        float acc[8][4];
        #pragma unroll
        for (int i = 0; i < 8; i++)
            #pragma unroll
            for (int j = 0; j < 4; j++) acc[i][j] = 0.f;

        #pragma unroll 8
        for (int k = 0; k < HD; k++) {
            float4 f0 = *(const float4*)&fsT[k * 128 + ty * 8];
            float4 f1 = *(const float4*)&fsT[k * 128 + ty * 8 + 4];
            float4 w = *(const float4*)&Ws[k * HD + tx * 4];
            float fv[8] = {f0.x, f0.y, f0.z, f0.w, f1.x, f1.y, f1.z, f1.w};
            float wv[4] = {w.x, w.y, w.z, w.w};
            #pragma unroll
            for (int i = 0; i < 8; i++)
                #pragma unroll
                for (int j = 0; j < 4; j++)
                    acc[i][j] = fmaf(fv[i], wv[j], acc[i][j]);
        }

        int rb = tile * 128 + ty * 8;
        #pragma unroll
        for (int i = 0; i < 8; i++) {
            float p = 0.f;
            #pragma unroll
            for (int j = 0; j < 4; j++)
                p = fmaf(fmaxf(acc[i][j] + bc1r[j], 0.f), wc2r[j], p);
            p += __shfl_down_sync(0xffffffffu, p, 8, 16);
            p += __shfl_down_sync(0xffffffffu, p, 4, 16);
            p += __shfl_down_sync(0xffffffffu, p, 2, 16);
            p += __shfl_down_sync(0xffffffffu, p, 1, 16);
            if (tx == 0 && rb + i < Mtot) g_zall[rb + i] = p + bc2;
        }
    }
}

// ---------------- phase B: 32-row tiles, y8 from cached feats + score + combine ----------------
__global__ void __launch_bounds__(256) k_scoreBfin(float* __restrict__ out,
                                                   const float* __restrict__ Wc1g,
                                                   const float* __restrict__ bc1g,
                                                   const float* __restrict__ wc2g,
                                                   const float* __restrict__ bc2g) {
    __shared__ float Ws[HD * HD];              // 16 KB
    __shared__ float fsT[HD * 32];             // 8 KB, [k][row]
    __shared__ float zs[32];
    int tid = threadIdx.x;
    int tx = tid & 15, ty = tid >> 4;          // GEMM: 4 cols x 2 rows
    int r = tid & 31, dgrp = tid >> 5;         // fill/combine: 8 thr per row, 8 dims each

    for (int i = tid; i < HD * HD; i += 256) Ws[i] = Wc1g[i];
    float bc1r[4], wc2r[4];
    #pragma unroll
    for (int j = 0; j < 4; j++) {
        bc1r[j] = __ldg(&bc1g[tx * 4 + j]);
        wc2r[j] = __ldg(&wc2g[tx * 4 + j]);
    }
    float bc2 = __ldg(&bc2g[0]);
    int Mhyp = g_Mhyp, nnz = g_nnz;

    int row = blockIdx.x * 32 + r;             // (t,n)
    int t = row >> 9, n = row & (N - 1);
    int deg = g_ne_cnt[n];
    int off = g_ne_off[n];
    int kb = dgrp * 8;

    // phase 1: y8 = softmax(z) . feats (feats cached from scoreA)
    {
        const float* zb = g_zall + t * nnz + off;
        const float* fb = g_feats + (t * nnz + off) * HD + kb;
        float M = -3.0e38f;
        for (int j = 0; j < deg; j++) M = fmaxf(M, zb[j]);
        float y[8];
        #pragma unroll
        for (int q = 0; q < 8; q++) y[q] = 0.f;
        float S = 0.f;
        for (int j = 0; j < deg; j++) {
            float w = fexp(zb[j] - M);
            S += w;
            float4 f0 = *(const float4*)&fb[j * HD];
            float4 f1 = *(const float4*)&fb[j * HD + 4];
            y[0] = fmaf(w, f0.x, y[0]); y[1] = fmaf(w, f0.y, y[1]);
            y[2] = fmaf(w, f0.z, y[2]); y[3] = fmaf(w, f0.w, y[3]);
            y[4] = fmaf(w, f1.x, y[4]); y[5] = fmaf(w, f1.y, y[5]);
            y[6] = fmaf(w, f1.z, y[6]); y[7] = fmaf(w, f1.w, y[7]);
        }
        float inv = 1.f / S;
        #pragma unroll
        for (int q = 0; q < 8; q++)
            fsT[(kb + q) * 32 + r] = y[q] * inv;
    }
    __syncthreads();

    // phase 2: GEMM 32x64 + z
    {
        float acc[2][4];
        #pragma unroll
        for (int i = 0; i < 2; i++)
            #pragma unroll
            for (int j = 0; j < 4; j++) acc[i][j] = 0.f;
        #pragma unroll 16
        for (int k = 0; k < HD; k++) {
            float2 f = *(const float2*)&fsT[k * 32 + ty * 2];
            float4 w = *(const float4*)&Ws[k * HD + tx * 4];
            float wv[4] = {w.x, w.y, w.z, w.w};
            #pragma unroll
            for (int j = 0; j < 4; j++) {
                acc[0][j] = fmaf(f.x, wv[j], acc[0][j]);
                acc[1][j] = fmaf(f.y, wv[j], acc[1][j]);
            }
        }
        #pragma unroll
        for (int i = 0; i < 2; i++) {
            float p = 0.f;
            #pragma unroll
            for (int j = 0; j < 4; j++)
                p = fmaf(fmaxf(acc[i][j] + bc1r[j], 0.f), wc2r[j], p);
            p += __shfl_down_sync(0xffffffffu, p, 8, 16);
            p += __shfl_down_sync(0xffffffffu, p, 4, 16);
            p += __shfl_down_sync(0xffffffffu, p, 2, 16);
            p += __shfl_down_sync(0xffffffffu, p, 1, 16);
            if (tx == 0) zs[ty * 2 + i] = p + bc2;
        }
    }
    __syncthreads();

    // phase 3: combine, 8 thr per row, 8 dims each
    float z2 = zs[r];
    float z1 = g_zall[Mhyp + row];
    float m2 = fmaxf(z1, z2);
    float w1 = fexp(z1 - m2), w2 = fexp(z2 - m2);
    float inv = 1.f / (w1 + w2);
    const float4* ip = (const float4*)&g_ind[row * HD + kb];
    float4* op = (float4*)&out[row * HD + kb];
    #pragma unroll
    for (int q = 0; q < 2; q++) {
        float4 iv = ip[q];
        float4 rr;
        rr.x = (w1 * iv.x + w2 * fsT[(kb + q * 4 + 0) * 32 + r]) * inv;
        rr.y = (w1 * iv.y + w2 * fsT[(kb + q * 4 + 1) * 32 + r]) * inv;
        rr.z = (w1 * iv.z + w2 * fsT[(kb + q * 4 + 2) * 32 + r]) * inv;
        rr.w = (w1 * iv.w + w2 * fsT[(kb + q * 4 + 3) * 32 + r]) * inv;
        op[q] = rr;
    }
}

// ---------------- launch ----------------
extern "C" void kernel_launch(void* const* d_in, const int* in_sizes, int n_in,
                              void* d_out, int out_size) {
    int off = (n_in >= 11) ? 1 : 0;
    const float* x   = (const float*)d_in[0];
    const int*   Hm  = (const int*)d_in[1];
    const int*   adj = (const int*)d_in[2];
    const float* W   = (const float*)d_in[3 + off];
    const float* ah  = (const float*)d_in[4 + off];
    const float* ai  = (const float*)d_in[5 + off];
    const float* Wc1 = (const float*)d_in[6 + off];
    const float* bc1 = (const float*)d_in[7 + off];
    const float* wc2 = (const float*)d_in[8 + off];
    const float* bc2 = (const float*)d_in[9 + off];
    float* outp = (float*)d_out;

    k_front<<<585, 256>>>(x, W, ah, ai, adj, Hm);
    k_mid<<<2048 + 256, 256>>>();
    k_scoreA<<<512, 256>>>(Wc1, bc1, wc2, bc2);
    k_scoreBfin<<<T * N / 32, 256>>>(outp, Wc1, bc1, wc2, bc2);
}

// round 10
// speedup vs baseline: 1.3491x; 1.3491x over previous
#include <cuda_runtime.h>
#include <math.h>

#define T 32
#define N 512
#define E 64
#define F 64
#define HD 64
#define SLOPE 0.2f

// ---------------- device scratch ----------------
__device__ float g_h[T * N * HD];       // 4 MB
__device__ float g_shyp[T * N];
__device__ float g_sind[T * N];
__device__ float g_emax[T * E];
__device__ float g_einv[T * E];
__device__ float g_ind[T * N * HD];     // 4 MB
__device__ int   g_adj_cnt[N];
__device__ int   g_adj_nbr[N * N];
__device__ int   g_ne_cnt[N];
__device__ int   g_ne_lst[N * E];
__device__ int   g_en_cnt[E];
__device__ int   g_en_lst[E * N];

// fast math: tolerance is 1e-3, __expf rel err ~1e-6
__device__ __forceinline__ float fexp(float v) { return __expf(v); }
__device__ __forceinline__ float elu1(float v) { return v > 0.f ? v : __expf(v) - 1.0f; }

// ---------------- fused front: h-GEMM + CSR builds (block-specialized) ----------------
__global__ void __launch_bounds__(256) k_front(const float* __restrict__ x,
                                               const float* __restrict__ W,
                                               const float* __restrict__ ah,
                                               const float* __restrict__ ai,
                                               const int* __restrict__ adj,
                                               const int* __restrict__ Hm) {
    int b = blockIdx.x;
    int tid = threadIdx.x;
    int lane = tid & 31;
    int wrp = tid >> 5;

    if (b < 512) {
        __shared__ float xs[32][65];
        __shared__ float ws[64][65];
        int r0 = b * 32;

        for (int i = tid; i < 32 * 64; i += 256) {
            int r = i >> 6, c = i & 63;
            xs[r][c] = x[(r0 + r) * F + c];
        }
        for (int i = tid; i < 64 * 64; i += 256) {
            int r = i >> 6, c = i & 63;
            ws[r][c] = W[i];
        }
        __syncthreads();

        int ty = tid >> 4, tx = tid & 15;
        float acc[2][4] = {{0.f,0.f,0.f,0.f},{0.f,0.f,0.f,0.f}};
        #pragma unroll 8
        for (int k = 0; k < 64; k++) {
            float xr0 = xs[ty * 2 + 0][k];
            float xr1 = xs[ty * 2 + 1][k];
            float wv[4];
            #pragma unroll
            for (int j = 0; j < 4; j++) wv[j] = ws[k][tx * 4 + j];
            #pragma unroll
            for (int j = 0; j < 4; j++) {
                acc[0][j] = fmaf(xr0, wv[j], acc[0][j]);
                acc[1][j] = fmaf(xr1, wv[j], acc[1][j]);
            }
        }
        __syncthreads();
        #pragma unroll
        for (int i = 0; i < 2; i++) {
            int r = ty * 2 + i;
            #pragma unroll
            for (int j = 0; j < 4; j++) xs[r][tx * 4 + j] = acc[i][j];
            float4 v = make_float4(acc[i][0], acc[i][1], acc[i][2], acc[i][3]);
            *(float4*)&g_h[(r0 + r) * HD + tx * 4] = v;
        }
        __syncthreads();

        int row = tid >> 3, oct = tid & 7;
        float sh = 0.f, si = 0.f;
        #pragma unroll
        for (int k = 0; k < 8; k++) {
            float v = xs[row][oct * 8 + k];
            sh = fmaf(v, __ldg(&ah[oct * 8 + k]), sh);
            si = fmaf(v, __ldg(&ai[oct * 8 + k]), si);
        }
        #pragma unroll
        for (int o = 4; o > 0; o >>= 1) {
            sh += __shfl_xor_sync(0xffffffffu, sh, o);
            si += __shfl_xor_sync(0xffffffffu, si, o);
        }
        if (oct == 0) {
            g_shyp[r0 + row] = sh >= 0.f ? sh : SLOPE * sh;
            g_sind[r0 + row] = si >= 0.f ? si : SLOPE * si;
        }
    } else if (b < 576) {                      // adjacency CSR
        int i = (b - 512) * 8 + wrp;
        int cnt = 0;
        #pragma unroll
        for (int c = 0; c < N / 32; c++) {
            int j = c * 32 + lane;
            bool m = adj[i * N + j] != 0;
            unsigned bl = __ballot_sync(0xffffffffu, m);
            if (m) g_adj_nbr[i * N + cnt + __popc(bl & ((1u << lane) - 1u))] = j;
            cnt += __popc(bl);
        }
        if (lane == 0) g_adj_cnt[i] = cnt;
    } else if (b < 584) {                      // edge -> member nodes
        int e = (b - 576) * 8 + wrp;
        int cnt = 0;
        #pragma unroll
        for (int c = 0; c < N / 32; c++) {
            int n = c * 32 + lane;
            bool m = Hm[n * E + e] != 0;
            unsigned bl = __ballot_sync(0xffffffffu, m);
            if (m) g_en_lst[e * N + cnt + __popc(bl & ((1u << lane) - 1u))] = n;
            cnt += __popc(bl);
        }
        if (lane == 0) g_en_cnt[e] = cnt;
    } else {                                   // node -> member edges (warp ballot, 16 nodes/warp-iter)
        // 8 warps cover 512 nodes: warp w handles nodes w*64..w*64+63, 2 ballots each (E=64)
        for (int nn = wrp * 64; nn < wrp * 64 + 64; nn++) {
            int cnt = 0;
            #pragma unroll
            for (int c = 0; c < 2; c++) {
                int e = c * 32 + lane;
                bool m = Hm[nn * E + e] != 0;
                unsigned bl = __ballot_sync(0xffffffffu, m);
                if (m) g_ne_lst[nn * E + cnt + __popc(bl & ((1u << lane) - 1u))] = e;
                cnt += __popc(bl);
            }
            if (lane == 0) g_ne_cnt[nn] = cnt;
        }
    }
}

// ---------------- fused: industry (warp-per-row, 8-wide MLP) + hyperedge stats ----------------
__global__ void __launch_bounds__(256) k_mid() {
    int b = blockIdx.x;
    int tid = threadIdx.x;
    int lane = tid & 31;
    int wrp = tid >> 5;
    if (b < 2048) {
        __shared__ float smw[8][512];
        int row = b * 8 + wrp;
        int t = row >> 9;
        int i = row & (N - 1);
        int deg = g_adj_cnt[i];
        const int* nbr = g_adj_nbr + i * N;
        const float* si = g_sind + t * N;

        float m = -3.0e38f;
        for (int k = lane; k < deg; k += 32) m = fmaxf(m, si[nbr[k]]);
        #pragma unroll
        for (int o = 16; o > 0; o >>= 1) m = fmaxf(m, __shfl_xor_sync(0xffffffffu, m, o));
        float s = 0.f;
        for (int k = lane; k < deg; k += 32) {
            float w = fexp(si[nbr[k]] - m);
            smw[wrp][k] = w;
            s += w;
        }
        #pragma unroll
        for (int o = 16; o > 0; o >>= 1) s += __shfl_xor_sync(0xffffffffu, s, o);
        float inv = 1.f / s;
        __syncwarp();

        const float* hb = g_h + t * N * HD;
        float2 ac[8];
        #pragma unroll
        for (int u = 0; u < 8; u++) ac[u] = make_float2(0.f, 0.f);
        int k = 0;
        for (; k + 8 <= deg; k += 8) {
            #pragma unroll
            for (int u = 0; u < 8; u++) {
                float w = smw[wrp][k + u];
                float2 hv = *(const float2*)&hb[nbr[k + u] * HD + lane * 2];
                ac[u].x = fmaf(w, hv.x, ac[u].x);
                ac[u].y = fmaf(w, hv.y, ac[u].y);
            }
        }
        for (; k < deg; k++) {
            float w = smw[wrp][k];
            float2 hv = *(const float2*)&hb[nbr[k] * HD + lane * 2];
            ac[0].x = fmaf(w, hv.x, ac[0].x);
            ac[0].y = fmaf(w, hv.y, ac[0].y);
        }
        float2 r;
        r.x = (((ac[0].x + ac[1].x) + (ac[2].x + ac[3].x)) +
               ((ac[4].x + ac[5].x) + (ac[6].x + ac[7].x))) * inv;
        r.y = (((ac[0].y + ac[1].y) + (ac[2].y + ac[3].y)) +
               ((ac[4].y + ac[5].y) + (ac[6].y + ac[7].y))) * inv;
        *(float2*)&g_ind[row * HD + lane * 2] = r;
    } else {
        int w = (b - 2048) * 8 + wrp;
        int t = w / E, e = w % E;
        int cnt = g_en_cnt[e];
        const int* lst = g_en_lst + e * N;
        const float* sh = g_shyp + t * N;
        float m = -3.0e38f;
        for (int i = lane; i < cnt; i += 32) m = fmaxf(m, sh[lst[i]]);
        #pragma unroll
        for (int o = 16; o > 0; o >>= 1) m = fmaxf(m, __shfl_xor_sync(0xffffffffu, m, o));
        float s = 0.f;
        for (int i = lane; i < cnt; i += 32) s += fexp(sh[lst[i]] - m);
        #pragma unroll
        for (int o = 16; o > 0; o >>= 1) s += __shfl_xor_sync(0xffffffffu, s, o);
        if (lane == 0) { g_emax[w] = m; g_einv[w] = 1.f / s; }
    }
}

// ---------------- fused scorer: feats + z (GEMM) + y8 + pair GEMM + combine, all in-block ----------
// Block owns 32 (t,n) rows (same t). Dynamic smem layout (floats unless noted):
//   Ws[4096] | fsT[64*132] | zhyp[32*64] | zfin[64] | loff[33] (int) | degs[32] (int) | i2m[2048] (u16)
#define FST_STRIDE 132
#define SC_SMEM_BYTES ((4096 + 64*FST_STRIDE + 32*64 + 64) * 4 + (33 + 32) * 4 + 2048 * 2 + 64)

__global__ void __launch_bounds__(256) k_score(float* __restrict__ out,
                                               const float* __restrict__ Wc1g,
                                               const float* __restrict__ bc1g,
                                               const float* __restrict__ wc2g,
                                               const float* __restrict__ bc2g) {
    extern __shared__ float sm[];
    float* Ws   = sm;                          // 4096
    float* fsT  = Ws + 4096;                   // 64*132, [k][col]
    float* zhyp = fsT + 64 * FST_STRIDE;       // 32*64, [r][j]
    float* zfin = zhyp + 32 * 64;              // 64
    int*   loff = (int*)(zfin + 64);           // 33
    int*   degs = loff + 33;                   // 32
    unsigned short* i2m = (unsigned short*)(degs + 32);  // 2048

    int tid = threadIdx.x;
    int lane = tid & 31;
    int tx = tid & 15, ty = tid >> 4;          // GEMM mapping
    int row0 = blockIdx.x * 32;
    int t = row0 >> 9;
    int n0 = row0 & (N - 1);

    for (int i = tid; i < HD * HD; i += 256) Ws[i] = Wc1g[i];
    float bc1r[4], wc2r[4];
    #pragma unroll
    for (int j = 0; j < 4; j++) {
        bc1r[j] = __ldg(&bc1g[tx * 4 + j]);
        wc2r[j] = __ldg(&wc2g[tx * 4 + j]);
    }
    float bc2 = __ldg(&bc2g[0]);

    // per-row degrees + exclusive offsets (warp 0)
    if (tid < 32) {
        int d = g_ne_cnt[n0 + tid];
        degs[tid] = d;
        int s = d;
        #pragma unroll
        for (int o = 1; o < 32; o <<= 1) {
            int v = __shfl_up_sync(0xffffffffu, s, o);
            if (lane >= o) s += v;
        }
        loff[tid + 1] = s;
        if (tid == 0) loff[0] = 0;
    }
    __syncthreads();
    int total = loff[32];
    if (tid < 32) {
        int o = loff[tid], d = degs[tid];
        for (int j = 0; j < d; j++) i2m[o + j] = (unsigned short)((tid << 6) | j);
    }
    __syncthreads();
    bool fast = (total <= 128);

    // ---- phase 1: hyper feats + GEMM -> zhyp (chunks of 128 work items) ----
    for (int base = 0; base < total; base += 128) {
        __syncthreads();
        int c = tid & 127, half = tid >> 7;
        int m = base + c;
        int kb = half * 32;
        if (m < total) {
            int v = i2m[m];
            int r = v >> 6, j = v & 63;
            int e = g_ne_lst[(n0 + r) * E + j];
            float alpha = fexp(g_shyp[row0 + r] - g_emax[t * E + e]) * g_einv[t * E + e];
            const float4* hp = (const float4*)&g_h[(row0 + r) * HD + kb];
            #pragma unroll
            for (int q = 0; q < 8; q++) {
                float4 hv = hp[q];
                fsT[(kb + q * 4 + 0) * FST_STRIDE + c] = elu1(alpha * hv.x);
                fsT[(kb + q * 4 + 1) * FST_STRIDE + c] = elu1(alpha * hv.y);
                fsT[(kb + q * 4 + 2) * FST_STRIDE + c] = elu1(alpha * hv.z);
                fsT[(kb + q * 4 + 3) * FST_STRIDE + c] = elu1(alpha * hv.w);
            }
        } else {
            #pragma unroll
            for (int q = 0; q < 32; q++) fsT[(kb + q) * FST_STRIDE + c] = 0.f;
        }
        __syncthreads();

        float acc[8][4];
        #pragma unroll
        for (int i = 0; i < 8; i++)
            #pragma unroll
            for (int j = 0; j < 4; j++) acc[i][j] = 0.f;
        #pragma unroll 8
        for (int k = 0; k < HD; k++) {
            float4 f0 = *(const float4*)&fsT[k * FST_STRIDE + ty * 8];
            float4 f1 = *(const float4*)&fsT[k * FST_STRIDE + ty * 8 + 4];
            float4 w = *(const float4*)&Ws[k * HD + tx * 4];
            float fv[8] = {f0.x, f0.y, f0.z, f0.w, f1.x, f1.y, f1.z, f1.w};
            float wv[4] = {w.x, w.y, w.z, w.w};
            #pragma unroll
            for (int i = 0; i < 8; i++)
                #pragma unroll
                for (int j = 0; j < 4; j++)
                    acc[i][j] = fmaf(fv[i], wv[j], acc[i][j]);
        }
        #pragma unroll
        for (int i = 0; i < 8; i++) {
            float p = 0.f;
            #pragma unroll
            for (int j = 0; j < 4; j++)
                p = fmaf(fmaxf(acc[i][j] + bc1r[j], 0.f), wc2r[j], p);
            p += __shfl_down_sync(0xffffffffu, p, 8, 16);
            p += __shfl_down_sync(0xffffffffu, p, 4, 16);
            p += __shfl_down_sync(0xffffffffu, p, 2, 16);
            p += __shfl_down_sync(0xffffffffu, p, 1, 16);
            if (tx == 0) {
                int m2 = base + ty * 8 + i;
                if (m2 < total) {
                    int v = i2m[m2];
                    zhyp[(v >> 6) * 64 + (v & 63)] = p + bc2;
                }
            }
        }
    }
    __syncthreads();

    // ---- phase 2: y8 per row (8 threads/row, 8 dims each) ----
    int r2 = tid >> 3, oct = tid & 7, kb2 = oct * 8;
    int row = row0 + r2;
    int deg = degs[r2];
    float y[8], indv[8];
    {
        const float4* ip = (const float4*)&g_ind[row * HD + kb2];
        float4 i0 = ip[0], i1 = ip[1];
        indv[0] = i0.x; indv[1] = i0.y; indv[2] = i0.z; indv[3] = i0.w;
        indv[4] = i1.x; indv[5] = i1.y; indv[6] = i1.z; indv[7] = i1.w;

        float M = -3.0e38f;
        for (int j = 0; j < deg; j++) M = fmaxf(M, zhyp[r2 * 64 + j]);
        float S = 0.f;
        #pragma unroll
        for (int q = 0; q < 8; q++) y[q] = 0.f;
        if (fast) {
            int o = loff[r2];
            for (int j = 0; j < deg; j++) {
                float w = fexp(zhyp[r2 * 64 + j] - M);
                S += w;
                int c = o + j;
                #pragma unroll
                for (int q = 0; q < 8; q++)
                    y[q] = fmaf(w, fsT[(kb2 + q) * FST_STRIDE + c], y[q]);
            }
        } else {
            float shn = g_shyp[row];
            const float4* hp = (const float4*)&g_h[row * HD + kb2];
            float4 h0 = hp[0], h1 = hp[1];
            float h8[8] = {h0.x, h0.y, h0.z, h0.w, h1.x, h1.y, h1.z, h1.w};
            const int* el = g_ne_lst + (n0 + r2) * E;
            for (int j = 0; j < deg; j++) {
                float w = fexp(zhyp[r2 * 64 + j] - M);
                S += w;
                int e = el[j];
                float alpha = fexp(shn - g_emax[t * E + e]) * g_einv[t * E + e];
                #pragma unroll
                for (int q = 0; q < 8; q++)
                    y[q] = fmaf(w, elu1(alpha * h8[q]), y[q]);
            }
        }
        float invS = 1.f / S;
        #pragma unroll
        for (int q = 0; q < 8; q++) y[q] *= invS;
    }
    __syncthreads();   // all fsT reads done before overwrite

    // write industry feats -> cols 0..31, y8 feats -> cols 32..63
    #pragma unroll
    for (int q = 0; q < 8; q++) {
        fsT[(kb2 + q) * FST_STRIDE + r2] = indv[q];
        fsT[(kb2 + q) * FST_STRIDE + 32 + r2] = y[q];
    }
    __syncthreads();

    // ---- phase 3: GEMM over 64 rows (industry | y8) -> zfin ----
    {
        float acc[4][4];
        #pragma unroll
        for (int i = 0; i < 4; i++)
            #pragma unroll
            for (int j = 0; j < 4; j++) acc[i][j] = 0.f;
        #pragma unroll 8
        for (int k = 0; k < HD; k++) {
            float4 f = *(const float4*)&fsT[k * FST_STRIDE + ty * 4];
            float4 w = *(const float4*)&Ws[k * HD + tx * 4];
            float fv[4] = {f.x, f.y, f.z, f.w};
            float wv[4] = {w.x, w.y, w.z, w.w};
            #pragma unroll
            for (int i = 0; i < 4; i++)
                #pragma unroll
                for (int j = 0; j < 4; j++)
                    acc[i][j] = fmaf(fv[i], wv[j], acc[i][j]);
        }
        #pragma unroll
        for (int i = 0; i < 4; i++) {
            float p = 0.f;
            #pragma unroll
            for (int j = 0; j < 4; j++)
                p = fmaf(fmaxf(acc[i][j] + bc1r[j], 0.f), wc2r[j], p);
            p += __shfl_down_sync(0xffffffffu, p, 8, 16);
            p += __shfl_down_sync(0xffffffffu, p, 4, 16);
            p += __shfl_down_sync(0xffffffffu, p, 2, 16);
            p += __shfl_down_sync(0xffffffffu, p, 1, 16);
            if (tx == 0) zfin[ty * 4 + i] = p + bc2;
        }
    }
    __syncthreads();

    // ---- phase 4: combine (registers only) ----
    float z1 = zfin[r2], z2 = zfin[32 + r2];
    float m2 = fmaxf(z1, z2);
    float w1 = fexp(z1 - m2), w2 = fexp(z2 - m2);
    float inv = 1.f / (w1 + w2);
    float4 o0, o1;
    o0.x = (w1 * indv[0] + w2 * y[0]) * inv;
    o0.y = (w1 * indv[1] + w2 * y[1]) * inv;
    o0.z = (w1 * indv[2] + w2 * y[2]) * inv;
    o0.w = (w1 * indv[3] + w2 * y[3]) * inv;
    o1.x = (w1 * indv[4] + w2 * y[4]) * inv;
    o1.y = (w1 * indv[5] + w2 * y[5]) * inv;
    o1.z = (w1 * indv[6] + w2 * y[6]) * inv;
    o1.w = (w1 * indv[7] + w2 * y[7]) * inv;
    float4* op = (float4*)&out[row * HD + kb2];
    op[0] = o0;
    op[1] = o1;
}

// ---------------- launch ----------------
extern "C" void kernel_launch(void* const* d_in, const int* in_sizes, int n_in,
                              void* d_out, int out_size) {
    int off = (n_in >= 11) ? 1 : 0;
    const float* x   = (const float*)d_in[0];
    const int*   Hm  = (const int*)d_in[1];
    const int*   adj = (const int*)d_in[2];
    const float* W   = (const float*)d_in[3 + off];
    const float* ah  = (const float*)d_in[4 + off];
    const float* ai  = (const float*)d_in[5 + off];
    const float* Wc1 = (const float*)d_in[6 + off];
    const float* bc1 = (const float*)d_in[7 + off];
    const float* wc2 = (const float*)d_in[8 + off];
    const float* bc2 = (const float*)d_in[9 + off];
    float* outp = (float*)d_out;

    cudaFuncSetAttribute(k_score, cudaFuncAttributeMaxDynamicSharedMemorySize, SC_SMEM_BYTES);

    k_front<<<585, 256>>>(x, W, ah, ai, adj, Hm);
    k_mid<<<2048 + 256, 256>>>();
    k_score<<<T * N / 32, 256, SC_SMEM_BYTES>>>(outp, Wc1, bc1, wc2, bc2);
}